// round 8
// baseline (speedup 1.0000x reference)
#include <cuda_runtime.h>
#include <cstdint>

// Problem constants
#define B_  8
#define N_  1024
#define NTOT 8192
#define INV_TEMP 10.0f
#define LN_EPS 1e-5f

// scratch: raw matvec results [NTOT][64] + per-patch spike mass [NTOT]
__device__ float g_raw[NTOT * 64];
__device__ float g_ps[NTOT];

// ============ Kernel 1: pure streaming matvec (no smem, no barriers) ============
__global__ __launch_bounds__(256)
void scs_matvec(const float* __restrict__ spikes,
                const float* __restrict__ Wd) {
    const int blk = blockIdx.x;          // patch tile g = b*1024 + n
    const int tid = threadIdx.x;
    const int b   = blk >> 10;
    const int n   = blk & 1023;
    const int py  = n >> 5;
    const int px  = n & 31;

    // ---- per-warp direct patch load: lane (tid&15) gets patch float4 jp ----
    const int jp = tid & 15;
    const float4* sp = (const float4*)(spikes + ((size_t)b << 16)
                                       + ((py << 3) + (jp >> 1)) * 256
                                       + (px << 3) + ((jp & 1) << 2));
    const float4 p = __ldg(sp);

    // ---- warp-contiguous streaming W loads (512B per warp instruction) ----
    const float4* Wp = (const float4*)(Wd + ((size_t)blk << 12));
    const float4 w0 = __ldcs(Wp + tid);
    const float4 w1 = __ldcs(Wp + tid + 256);
    const float4 w2 = __ldcs(Wp + tid + 512);
    const float4 w3 = __ldcs(Wp + tid + 768);

    float a0 = w0.x * p.x + w0.y * p.y + w0.z * p.z + w0.w * p.w;
    float a1 = w1.x * p.x + w1.y * p.y + w1.z * p.z + w1.w * p.w;
    float a2 = w2.x * p.x + w2.y * p.y + w2.z * p.z + w2.w * p.w;
    float a3 = w3.x * p.x + w3.y * p.y + w3.z * p.z + w3.w * p.w;
    float ps = p.x + p.y + p.z + p.w;    // patch spike mass rides the same chain

#pragma unroll
    for (int o = 1; o < 16; o <<= 1) {
        a0 += __shfl_xor_sync(0xffffffffu, a0, o);
        a1 += __shfl_xor_sync(0xffffffffu, a1, o);
        a2 += __shfl_xor_sync(0xffffffffu, a2, o);
        a3 += __shfl_xor_sync(0xffffffffu, a3, o);
        ps += __shfl_xor_sync(0xffffffffu, ps, o);
    }
    if (jp == 0) {
        const int r0 = tid >> 4;         // 0..15
        float* dst = g_raw + ((size_t)blk << 6);
        dst[r0]      = a0;
        dst[r0 + 16] = a1;
        dst[r0 + 32] = a2;
        dst[r0 + 48] = a3;
    }
    if (tid == 0) g_ps[blk] = ps;
}

// ============ Kernel 2: LN + softmax + affine + fold. One warp = TWO patches ============
__global__ __launch_bounds__(256)
void scs_epilogue(const float* __restrict__ gamma,
                  const float* __restrict__ beta,
                  const float* __restrict__ gates,
                  const float* __restrict__ biases,
                  float* __restrict__ out) {
    const int w  = threadIdx.x >> 5;
    const int l  = threadIdx.x & 31;
    const int l2 = l + 32;
    const int g0 = (((blockIdx.x << 3) + w) << 1);   // even patch tile
    const int g1 = g0 + 1;

    // front-batched coalesced loads (L2-resident scratch)
    const float* rp = g_raw + ((size_t)g0 << 6);
    const float v00 = rp[l];
    const float v01 = rp[l2];
    const float v10 = rp[64 + l];
    const float v11 = rp[64 + l2];
    const float ps0 = g_ps[g0];
    const float ps1 = g_ps[g1];
    const float gm0 = __ldg(&gamma[l]),  gm1 = __ldg(&gamma[l2]);
    const float bt0 = __ldg(&beta[l]),   bt1 = __ldg(&beta[l2]);

    // chain 1: sum & sumsq for both patches, interleaved
    float sm0 = v00 + v01, s20 = v00 * v00 + v01 * v01;
    float sm1 = v10 + v11, s21 = v10 * v10 + v11 * v11;
#pragma unroll
    for (int o = 16; o > 0; o >>= 1) {
        sm0 += __shfl_xor_sync(0xffffffffu, sm0, o);
        s20 += __shfl_xor_sync(0xffffffffu, s20, o);
        sm1 += __shfl_xor_sync(0xffffffffu, sm1, o);
        s21 += __shfl_xor_sync(0xffffffffu, s21, o);
    }
    const float mu0 = sm0 * (1.0f / 64.0f);
    const float mu1 = sm1 * (1.0f / 64.0f);
    const float rstd0 = rsqrtf(s20 * (1.0f / 64.0f) - mu0 * mu0 + LN_EPS);
    const float rstd1 = rsqrtf(s21 * (1.0f / 64.0f) - mu1 * mu1 + LN_EPS);

    const float z00 = ((v00 - mu0) * rstd0 * gm0 + bt0) * INV_TEMP;
    const float z01 = ((v01 - mu0) * rstd0 * gm1 + bt1) * INV_TEMP;
    const float z10 = ((v10 - mu1) * rstd1 * gm0 + bt0) * INV_TEMP;
    const float z11 = ((v11 - mu1) * rstd1 * gm1 + bt1) * INV_TEMP;

    // chain 2: max, both patches interleaved
    float mx0 = fmaxf(z00, z01);
    float mx1 = fmaxf(z10, z11);
#pragma unroll
    for (int o = 16; o > 0; o >>= 1) {
        mx0 = fmaxf(mx0, __shfl_xor_sync(0xffffffffu, mx0, o));
        mx1 = fmaxf(mx1, __shfl_xor_sync(0xffffffffu, mx1, o));
    }
    const float e00 = __expf(z00 - mx0);
    const float e01 = __expf(z01 - mx0);
    const float e10 = __expf(z10 - mx1);
    const float e11 = __expf(z11 - mx1);

    // chain 3: exp-sum, both patches interleaved
    float se0 = e00 + e01;
    float se1 = e10 + e11;
#pragma unroll
    for (int o = 16; o > 0; o >>= 1) {
        se0 += __shfl_xor_sync(0xffffffffu, se0, o);
        se1 += __shfl_xor_sync(0xffffffffu, se1, o);
    }

    const int n0 = g0 & 1023;
    const int n1 = n0 + 1;
    const float sc0 = (__ldg(&gates[n0]) * ps0 + __ldg(&biases[n0])) / se0;
    const float sc1 = (__ldg(&gates[n1]) * ps1 + __ldg(&biases[n1])) / se1;

    // fold-store both patches (adjacent columns)
    const int b  = g0 >> 10;
    const int py = n0 >> 5;
    const int px = n0 & 31;          // even
    float* ob = out + ((size_t)b << 16) + (py << 3) * 256 + (px << 3);
    ob[(l  >> 3) * 256 + (l  & 7)]     = e00 * sc0;
    ob[(l2 >> 3) * 256 + (l2 & 7)]     = e01 * sc0;
    ob[(l  >> 3) * 256 + (l  & 7) + 8] = e10 * sc1;
    ob[(l2 >> 3) * 256 + (l2 & 7) + 8] = e11 * sc1;
}

extern "C" void kernel_launch(void* const* d_in, const int* in_sizes, int n_in,
                              void* d_out, int out_size) {
    const float* spikes = (const float*)d_in[0];
    const float* Wd     = (const float*)d_in[1];
    const float* gamma  = (const float*)d_in[2];
    const float* beta   = (const float*)d_in[3];
    const float* gates  = (const float*)d_in[4];
    const float* biases = (const float*)d_in[5];
    float* out = (float*)d_out;

    scs_matvec<<<NTOT, 256>>>(spikes, Wd);
    scs_epilogue<<<NTOT / 16, 256>>>(gamma, beta, gates, biases, out);
}